// round 2
// baseline (speedup 1.0000x reference)
#include <cuda_runtime.h>
#include <cuda_bf16.h>

#define NX 2048
#define NY 4096

// Coefficient tables: [slot 0..2][index]. slot = position within 3-pt stencil.
// Stencil base for point k is s = clamp(k-1, 0, N-3); tables hold the
// left/inner/right one-sided variants baked in per k.
__device__ float g_c1x[3][NX];
__device__ float g_c2x[3][NX];
__device__ float g_c1y[3][NY];
__device__ float g_c2y[3][NY];

__device__ __forceinline__ void compute_coeffs(const float* __restrict__ g, int N, int k,
                                               float c1[3], float c2[3]) {
    int s = min(max(k - 1, 0), N - 3);
    float g0 = g[s], g1 = g[s + 1], g2 = g[s + 2];
    float ha = g1 - g0;
    float hb = g2 - g1;
    float sab = ha + hb;
    float inv = 1.0f / (ha * hb * sab);
    float i_a  = hb  * inv;   // 1/(ha*(ha+hb))
    float i_ab = sab * inv;   // 1/(ha*hb)
    float i_b  = ha  * inv;   // 1/(hb*(ha+hb))
    // second derivative: same form for left/inner/right
    c2[0] = 2.0f * i_a;
    c2[1] = -2.0f * i_ab;
    c2[2] = 2.0f * i_b;
    if (k == 0) {
        // left one-sided
        c1[0] = -(2.0f * ha + hb) * i_a;
        c1[1] = sab * i_ab;
        c1[2] = -ha * i_b;
    } else if (k == N - 1) {
        // right one-sided
        c1[0] = hb * i_a;
        c1[1] = -sab * i_ab;
        c1[2] = (ha + 2.0f * hb) * i_b;
    } else {
        // centered (nonuniform)
        c1[0] = -hb * i_a;
        c1[1] = (hb - ha) * i_ab;
        c1[2] = ha * i_b;
    }
}

__global__ void coeff_kernel(const float* __restrict__ x, const float* __restrict__ y) {
    int k = blockIdx.x * blockDim.x + threadIdx.x;
    if (k < NY) {
        float c1[3], c2[3];
        compute_coeffs(y, NY, k, c1, c2);
        g_c1y[0][k] = c1[0]; g_c1y[1][k] = c1[1]; g_c1y[2][k] = c1[2];
        g_c2y[0][k] = c2[0]; g_c2y[1][k] = c2[1]; g_c2y[2][k] = c2[2];
    }
    if (k < NX) {
        float c1[3], c2[3];
        compute_coeffs(x, NX, k, c1, c2);
        g_c1x[0][k] = c1[0]; g_c1x[1][k] = c1[1]; g_c1x[2][k] = c1[2];
        g_c2x[0][k] = c2[0]; g_c2x[1][k] = c2[1]; g_c2x[2][k] = c2[2];
    }
}

__global__ __launch_bounds__(256) void rhs_kernel(const float* __restrict__ state,
                                                  const float* __restrict__ mu_p,
                                                  float* __restrict__ out) {
    int jg = blockIdx.x * blockDim.x + threadIdx.x;   // j-group (4 j's per thread)
    int i  = blockIdx.y * blockDim.y + threadIdx.y;
    if (jg >= NY / 4 || i >= NX) return;
    int j0 = jg * 4;

    const float* __restrict__ u = state;
    const float* __restrict__ v = state + NX * NY;

    int sx = min(max(i - 1, 0), NX - 3);
    int ci = i - sx;  // which of the 3 x-stencil rows is the center row

    // x-stencil rows (float4 over 4 consecutive j)
    const float4 ux0 = *(const float4*)(u + sx * NY + j0);
    const float4 ux1 = *(const float4*)(u + (sx + 1) * NY + j0);
    const float4 ux2 = *(const float4*)(u + (sx + 2) * NY + j0);
    const float4 vx0 = *(const float4*)(v + sx * NY + j0);
    const float4 vx1 = *(const float4*)(v + (sx + 1) * NY + j0);
    const float4 vx2 = *(const float4*)(v + (sx + 2) * NY + j0);

    // center row = one of the three x rows
    float4 uc4 = (ci == 0) ? ux0 : ((ci == 2) ? ux2 : ux1);
    float4 vc4 = (ci == 0) ? vx0 : ((ci == 2) ? vx2 : vx1);

    // y-edge scalars
    float uL = (j0 > 0)      ? u[i * NY + j0 - 1] : 0.0f;
    float uR = (j0 + 4 < NY) ? u[i * NY + j0 + 4] : 0.0f;
    float vL = (j0 > 0)      ? v[i * NY + j0 - 1] : 0.0f;
    float vR = (j0 + 4 < NY) ? v[i * NY + j0 + 4] : 0.0f;

    // coefficients
    float4 c1y0 = *(const float4*)&g_c1y[0][j0];
    float4 c1y1 = *(const float4*)&g_c1y[1][j0];
    float4 c1y2 = *(const float4*)&g_c1y[2][j0];
    float4 c2y0 = *(const float4*)&g_c2y[0][j0];
    float4 c2y1 = *(const float4*)&g_c2y[1][j0];
    float4 c2y2 = *(const float4*)&g_c2y[2][j0];
    float c1x0 = g_c1x[0][i], c1x1 = g_c1x[1][i], c1x2 = g_c1x[2][i];
    float c2x0 = g_c2x[0][i], c2x1 = g_c2x[1][i], c2x2 = g_c2x[2][i];

    float mu = mu_p[0];

    float u_vals[6] = {uL, uc4.x, uc4.y, uc4.z, uc4.w, uR};
    float v_vals[6] = {vL, vc4.x, vc4.y, vc4.z, vc4.w, vR};
    float AX0[4] = {ux0.x, ux0.y, ux0.z, ux0.w};
    float AX1[4] = {ux1.x, ux1.y, ux1.z, ux1.w};
    float AX2[4] = {ux2.x, ux2.y, ux2.z, ux2.w};
    float BX0[4] = {vx0.x, vx0.y, vx0.z, vx0.w};
    float BX1[4] = {vx1.x, vx1.y, vx1.z, vx1.w};
    float BX2[4] = {vx2.x, vx2.y, vx2.z, vx2.w};
    float C1Y0[4] = {c1y0.x, c1y0.y, c1y0.z, c1y0.w};
    float C1Y1[4] = {c1y1.x, c1y1.y, c1y1.z, c1y1.w};
    float C1Y2[4] = {c1y2.x, c1y2.y, c1y2.z, c1y2.w};
    float C2Y0[4] = {c2y0.x, c2y0.y, c2y0.z, c2y0.w};
    float C2Y1[4] = {c2y1.x, c2y1.y, c2y1.z, c2y1.w};
    float C2Y2[4] = {c2y2.x, c2y2.y, c2y2.z, c2y2.w};

    bool eL = (j0 == 0);
    bool eR = (j0 == NY - 4);

    float du[4], dv[4];
#pragma unroll
    for (int l = 0; l < 4; l++) {
        float f0 = u_vals[l], f1 = u_vals[l + 1], f2 = u_vals[l + 2];
        float g0 = v_vals[l], g1 = v_vals[l + 1], g2 = v_vals[l + 2];
        if (eL && l == 0) {  // one-sided stencil at j=0: points 0,1,2
            f0 = u_vals[1]; f1 = u_vals[2]; f2 = u_vals[3];
            g0 = v_vals[1]; g1 = v_vals[2]; g2 = v_vals[3];
        }
        if (eR && l == 3) {  // one-sided stencil at j=NY-1: points NY-3..NY-1
            f0 = u_vals[2]; f1 = u_vals[3]; f2 = u_vals[4];
            g0 = v_vals[2]; g1 = v_vals[3]; g2 = v_vals[4];
        }

        float d1yu = C1Y0[l] * f0 + C1Y1[l] * f1 + C1Y2[l] * f2;
        float d2yu = C2Y0[l] * f0 + C2Y1[l] * f1 + C2Y2[l] * f2;
        float d1yv = C1Y0[l] * g0 + C1Y1[l] * g1 + C1Y2[l] * g2;
        float d2yv = C2Y0[l] * g0 + C2Y1[l] * g1 + C2Y2[l] * g2;

        float d1xu = c1x0 * AX0[l] + c1x1 * AX1[l] + c1x2 * AX2[l];
        float d2xu = c2x0 * AX0[l] + c2x1 * AX1[l] + c2x2 * AX2[l];
        float d1xv = c1x0 * BX0[l] + c1x1 * BX1[l] + c1x2 * BX2[l];
        float d2xv = c2x0 * BX0[l] + c2x1 * BX1[l] + c2x2 * BX2[l];

        float ucen = u_vals[l + 1];
        float vcen = v_vals[l + 1];

        du[l] = mu * (d2yu + d2xu) - ucen * d1xu - vcen * d1yu + 0.01f;
        dv[l] = mu * (d2yv + d2xv) - ucen * d1xv - vcen * d1yv;

        int jj = j0 + l;
        if (jj == 0 || i == 0) { du[l] = 0.0f; dv[l] = 0.0f; }
        if (jj == NY - 1) du[l] = 0.0f;
    }

    float4 du4 = make_float4(du[0], du[1], du[2], du[3]);
    float4 dv4 = make_float4(dv[0], dv[1], dv[2], dv[3]);
    *(float4*)(out + i * NY + j0) = du4;
    *(float4*)(out + NX * NY + i * NY + j0) = dv4;
}

extern "C" void kernel_launch(void* const* d_in, const int* in_sizes, int n_in,
                              void* d_out, int out_size) {
    // inputs: 0=t(1), 1=state(2*NX*NY), 2=x(NX), 3=y(NY), 4=mu(1)
    const float* x_g   = (const float*)d_in[2];
    const float* y_g   = (const float*)d_in[3];
    const float* state = (const float*)d_in[1];
    const float* mu    = (const float*)d_in[4];
    float* out = (float*)d_out;

    coeff_kernel<<<(NY + 255) / 256, 256>>>(x_g, y_g);

    dim3 blk(32, 8);
    dim3 grd((NY / 4) / 32, NX / 8);
    rhs_kernel<<<grd, blk>>>(state, mu, out);
}

// round 3
// speedup vs baseline: 1.3691x; 1.3691x over previous
#include <cuda_runtime.h>
#include <cuda_bf16.h>

#define NX 2048
#define NY 4096
#define FULLMASK 0xffffffffu

// y-direction coefficient tables (per j, one-sidedness baked in at j=0 / j=NY-1)
__device__ float g_c1y[3][NY];
__device__ float g_c2y[3][NY];
// x-direction coefficients packed: cxA = {c1x0, c1x1, c1x2, c2x0}, cxB = {c2x1, c2x2, 0, 0}
__device__ float4 g_cxA[NX];
__device__ float4 g_cxB[NX];

__device__ __forceinline__ void compute_coeffs(const float* __restrict__ g, int N, int k,
                                               float c1[3], float c2[3]) {
    int s = min(max(k - 1, 0), N - 3);
    float g0 = g[s], g1 = g[s + 1], g2 = g[s + 2];
    float ha = g1 - g0;
    float hb = g2 - g1;
    float sab = ha + hb;
    float inv = 1.0f / (ha * hb * sab);
    float i_a  = hb  * inv;   // 1/(ha*(ha+hb))
    float i_ab = sab * inv;   // 1/(ha*hb)
    float i_b  = ha  * inv;   // 1/(hb*(ha+hb))
    c2[0] = 2.0f * i_a;
    c2[1] = -2.0f * i_ab;
    c2[2] = 2.0f * i_b;
    if (k == 0) {
        c1[0] = -(2.0f * ha + hb) * i_a;
        c1[1] = sab * i_ab;
        c1[2] = -ha * i_b;
    } else if (k == N - 1) {
        c1[0] = hb * i_a;
        c1[1] = -sab * i_ab;
        c1[2] = (ha + 2.0f * hb) * i_b;
    } else {
        c1[0] = -hb * i_a;
        c1[1] = (hb - ha) * i_ab;
        c1[2] = ha * i_b;
    }
}

__global__ void coeff_kernel(const float* __restrict__ x, const float* __restrict__ y) {
    int k = blockIdx.x * blockDim.x + threadIdx.x;
    if (k < NY) {
        float c1[3], c2[3];
        compute_coeffs(y, NY, k, c1, c2);
        g_c1y[0][k] = c1[0]; g_c1y[1][k] = c1[1]; g_c1y[2][k] = c1[2];
        g_c2y[0][k] = c2[0]; g_c2y[1][k] = c2[1]; g_c2y[2][k] = c2[2];
    }
    if (k < NX) {
        float c1[3], c2[3];
        compute_coeffs(x, NX, k, c1, c2);
        g_cxA[k] = make_float4(c1[0], c1[1], c1[2], c2[0]);
        g_cxB[k] = make_float4(c2[1], c2[2], 0.0f, 0.0f);
    }
}

// Each thread: 4 consecutive j (float4) x 4 consecutive i rows.
__global__ __launch_bounds__(128, 4) void rhs_kernel(const float* __restrict__ state,
                                                     const float* __restrict__ mu_p,
                                                     float* __restrict__ out) {
    const int lane = threadIdx.x;                       // 0..31, warp = one y-slice
    const int jg = blockIdx.x * 32 + lane;              // j-group
    const int j0 = jg * 4;
    const int it = blockIdx.y * blockDim.y + threadIdx.y;
    const int i0 = it * 4;

    const float* __restrict__ u = state;
    const float* __restrict__ v = state + NX * NY;

    // Load 6 state rows per field: global rows clamp(i0-1 .. i0+4)
    float4 U[6], V[6];
#pragma unroll
    for (int k = 0; k < 6; k++) {
        int r = min(max(i0 - 1 + k, 0), NX - 1);
        U[k] = *(const float4*)(u + (size_t)r * NY + j0);
        V[k] = *(const float4*)(v + (size_t)r * NY + j0);
    }

    // Warp-edge scalar neighbors (only lanes 0 / 31 actually load)
    float uLe[4], uRe[4], vLe[4], vRe[4];
    const bool haveL = (lane == 0) && (j0 > 0);
    const bool haveR = (lane == 31) && (j0 + 4 < NY);
#pragma unroll
    for (int m = 0; m < 4; m++) {
        int i = i0 + m;
        uLe[m] = haveL ? u[(size_t)i * NY + j0 - 1] : 0.0f;
        vLe[m] = haveL ? v[(size_t)i * NY + j0 - 1] : 0.0f;
        uRe[m] = haveR ? u[(size_t)i * NY + j0 + 4] : 0.0f;
        vRe[m] = haveR ? v[(size_t)i * NY + j0 + 4] : 0.0f;
    }

    // y-coefficients (once per thread, reused for 4 rows)
    float4 c1y0 = *(const float4*)&g_c1y[0][j0];
    float4 c1y1 = *(const float4*)&g_c1y[1][j0];
    float4 c1y2 = *(const float4*)&g_c1y[2][j0];
    float4 c2y0 = *(const float4*)&g_c2y[0][j0];
    float4 c2y1 = *(const float4*)&g_c2y[1][j0];
    float4 c2y2 = *(const float4*)&g_c2y[2][j0];
    const float C1Y0[4] = {c1y0.x, c1y0.y, c1y0.z, c1y0.w};
    const float C1Y1[4] = {c1y1.x, c1y1.y, c1y1.z, c1y1.w};
    const float C1Y2[4] = {c1y2.x, c1y2.y, c1y2.z, c1y2.w};
    const float C2Y0[4] = {c2y0.x, c2y0.y, c2y0.z, c2y0.w};
    const float C2Y1[4] = {c2y1.x, c2y1.y, c2y1.z, c2y1.w};
    const float C2Y2[4] = {c2y2.x, c2y2.y, c2y2.z, c2y2.w};

    const float mu = mu_p[0];
    const bool eL = (j0 == 0);
    const bool eR = (j0 == NY - 4);
    const bool firstB = (i0 == 0);
    const bool lastB = (i0 == NX - 4);

#pragma unroll
    for (int m = 0; m < 4; m++) {
        const int i = i0 + m;

        // select x-stencil rows (local index li = m except boundary blocks)
        float4 u0, u1, u2, v0, v1, v2;
        if (m == 0) {
            u0 = firstB ? U[1] : U[0]; u1 = firstB ? U[2] : U[1]; u2 = firstB ? U[3] : U[2];
            v0 = firstB ? V[1] : V[0]; v1 = firstB ? V[2] : V[1]; v2 = firstB ? V[3] : V[2];
        } else if (m == 3) {
            u0 = lastB ? U[2] : U[3]; u1 = lastB ? U[3] : U[4]; u2 = lastB ? U[4] : U[5];
            v0 = lastB ? V[2] : V[3]; v1 = lastB ? V[3] : V[4]; v2 = lastB ? V[4] : V[5];
        } else {
            u0 = U[m]; u1 = U[m + 1]; u2 = U[m + 2];
            v0 = V[m]; v1 = V[m + 1]; v2 = V[m + 2];
        }

        // center row (global row i) is always U[m+1] / V[m+1]
        const float4 uc = U[m + 1];
        const float4 vc = V[m + 1];

        // y-neighbors via warp shuffle, patched at warp edges
        float uLm = __shfl_up_sync(FULLMASK, uc.w, 1);
        float vLm = __shfl_up_sync(FULLMASK, vc.w, 1);
        float uRm = __shfl_down_sync(FULLMASK, uc.x, 1);
        float vRm = __shfl_down_sync(FULLMASK, vc.x, 1);
        if (lane == 0)  { uLm = uLe[m]; vLm = vLe[m]; }
        if (lane == 31) { uRm = uRe[m]; vRm = vRe[m]; }

        // x-coefficients for this row
        const float4 cA = g_cxA[i];
        const float4 cB = g_cxB[i];

        const float u_vals[6] = {uLm, uc.x, uc.y, uc.z, uc.w, uRm};
        const float v_vals[6] = {vLm, vc.x, vc.y, vc.z, vc.w, vRm};
        const float AX0[4] = {u0.x, u0.y, u0.z, u0.w};
        const float AX1[4] = {u1.x, u1.y, u1.z, u1.w};
        const float AX2[4] = {u2.x, u2.y, u2.z, u2.w};
        const float BX0[4] = {v0.x, v0.y, v0.z, v0.w};
        const float BX1[4] = {v1.x, v1.y, v1.z, v1.w};
        const float BX2[4] = {v2.x, v2.y, v2.z, v2.w};

        float du[4], dv[4];
#pragma unroll
        for (int l = 0; l < 4; l++) {
            float f0 = u_vals[l], f1 = u_vals[l + 1], f2 = u_vals[l + 2];
            float g0 = v_vals[l], g1 = v_vals[l + 1], g2 = v_vals[l + 2];
            if (eL && l == 0) {         // one-sided at j=0: points 0,1,2
                f0 = u_vals[1]; f1 = u_vals[2]; f2 = u_vals[3];
                g0 = v_vals[1]; g1 = v_vals[2]; g2 = v_vals[3];
            }
            if (eR && l == 3) {         // one-sided at j=NY-1: points NY-3..NY-1
                f0 = u_vals[2]; f1 = u_vals[3]; f2 = u_vals[4];
                g0 = v_vals[2]; g1 = v_vals[3]; g2 = v_vals[4];
            }

            float d1yu = C1Y0[l] * f0 + C1Y1[l] * f1 + C1Y2[l] * f2;
            float d2yu = C2Y0[l] * f0 + C2Y1[l] * f1 + C2Y2[l] * f2;
            float d1yv = C1Y0[l] * g0 + C1Y1[l] * g1 + C1Y2[l] * g2;
            float d2yv = C2Y0[l] * g0 + C2Y1[l] * g1 + C2Y2[l] * g2;

            float d1xu = cA.x * AX0[l] + cA.y * AX1[l] + cA.z * AX2[l];
            float d2xu = cA.w * AX0[l] + cB.x * AX1[l] + cB.y * AX2[l];
            float d1xv = cA.x * BX0[l] + cA.y * BX1[l] + cA.z * BX2[l];
            float d2xv = cA.w * BX0[l] + cB.x * BX1[l] + cB.y * BX2[l];

            float ucen = u_vals[l + 1];
            float vcen = v_vals[l + 1];

            du[l] = mu * (d2yu + d2xu) - ucen * d1xu - vcen * d1yu + 0.01f;
            dv[l] = mu * (d2yv + d2xv) - ucen * d1xv - vcen * d1yv;

            int jj = j0 + l;
            if (jj == 0 || i == 0) { du[l] = 0.0f; dv[l] = 0.0f; }
            if (jj == NY - 1) du[l] = 0.0f;
        }

        *(float4*)(out + (size_t)i * NY + j0) =
            make_float4(du[0], du[1], du[2], du[3]);
        *(float4*)(out + (size_t)NX * NY + (size_t)i * NY + j0) =
            make_float4(dv[0], dv[1], dv[2], dv[3]);
    }
}

extern "C" void kernel_launch(void* const* d_in, const int* in_sizes, int n_in,
                              void* d_out, int out_size) {
    // inputs: 0=t(1), 1=state(2*NX*NY), 2=x(NX), 3=y(NY), 4=mu(1)
    const float* x_g   = (const float*)d_in[2];
    const float* y_g   = (const float*)d_in[3];
    const float* state = (const float*)d_in[1];
    const float* mu    = (const float*)d_in[4];
    float* out = (float*)d_out;

    coeff_kernel<<<(NY + 255) / 256, 256>>>(x_g, y_g);

    dim3 blk(32, 4);                       // 128 threads
    dim3 grd((NY / 4) / 32, NX / (4 * 4)); // (32, 128)
    rhs_kernel<<<grd, blk>>>(state, mu, out);
}

// round 4
// speedup vs baseline: 1.4546x; 1.0624x over previous
#include <cuda_runtime.h>
#include <cuda_bf16.h>

#define NX 2048
#define NY 4096
#define FULLMASK 0xffffffffu

// kind: 0 = left one-sided, 1 = centered, 2 = right one-sided
__device__ __forceinline__ void stencil_coeffs(float g0, float g1, float g2, int kind,
                                               float c1[3], float c2[3]) {
    float ha = g1 - g0;
    float hb = g2 - g1;
    float sab = ha + hb;
    float inv = 1.0f / (ha * hb * sab);
    float i_a  = hb  * inv;   // 1/(ha*(ha+hb))
    float i_ab = sab * inv;   // 1/(ha*hb)
    float i_b  = ha  * inv;   // 1/(hb*(ha+hb))
    c2[0] = 2.0f * i_a;
    c2[1] = -2.0f * i_ab;
    c2[2] = 2.0f * i_b;
    if (kind == 0) {
        c1[0] = -(2.0f * ha + hb) * i_a;
        c1[1] = sab * i_ab;
        c1[2] = -ha * i_b;
    } else if (kind == 2) {
        c1[0] = hb * i_a;
        c1[1] = -sab * i_ab;
        c1[2] = (ha + 2.0f * hb) * i_b;
    } else {
        c1[0] = -hb * i_a;
        c1[1] = (hb - ha) * i_ab;
        c1[2] = ha * i_b;
    }
}

// Each thread: 4 consecutive j (float4) x 4 consecutive i rows. Coefficients
// computed inline from the grid vectors (no precompute kernel).
__global__ __launch_bounds__(128, 4) void rhs_kernel(const float* __restrict__ state,
                                                     const float* __restrict__ xg,
                                                     const float* __restrict__ yg,
                                                     const float* __restrict__ mu_p,
                                                     float* __restrict__ out) {
    const int lane = threadIdx.x;                       // 0..31, warp = one y-slice
    const int jg = blockIdx.x * 32 + lane;              // j-group
    const int j0 = jg * 4;
    const int it = blockIdx.y * blockDim.y + threadIdx.y;
    const int i0 = it * 4;

    const float* __restrict__ u = state;
    const float* __restrict__ v = state + NX * NY;

    // Load 6 state rows per field: global rows clamp(i0-1 .. i0+4)
    float4 U[6], V[6];
#pragma unroll
    for (int k = 0; k < 6; k++) {
        int r = min(max(i0 - 1 + k, 0), NX - 1);
        U[k] = *(const float4*)(u + (size_t)r * NY + j0);
        V[k] = *(const float4*)(v + (size_t)r * NY + j0);
    }

    // Grid points needed for coefficients
    float ys[6], xs[6];
#pragma unroll
    for (int t = 0; t < 6; t++) {
        ys[t] = yg[min(max(j0 - 1 + t, 0), NY - 1)];
        xs[t] = xg[min(max(i0 - 1 + t, 0), NX - 1)];
    }

    // Warp-edge scalar neighbors (only lanes 0 / 31 actually load)
    float uLe[4], uRe[4], vLe[4], vRe[4];
    const bool haveL = (lane == 0) && (j0 > 0);
    const bool haveR = (lane == 31) && (j0 + 4 < NY);
#pragma unroll
    for (int m = 0; m < 4; m++) {
        int i = i0 + m;
        uLe[m] = haveL ? u[(size_t)i * NY + j0 - 1] : 0.0f;
        vLe[m] = haveL ? v[(size_t)i * NY + j0 - 1] : 0.0f;
        uRe[m] = haveR ? u[(size_t)i * NY + j0 + 4] : 0.0f;
        vRe[m] = haveR ? v[(size_t)i * NY + j0 + 4] : 0.0f;
    }

    const bool eL = (j0 == 0);
    const bool eR = (j0 == NY - 4);
    const bool firstB = (i0 == 0);
    const bool lastB = (i0 == NX - 4);

    // y coefficients for the 4 j positions (static indexing after unroll)
    float C1Y0[4], C1Y1[4], C1Y2[4], C2Y0[4], C2Y1[4], C2Y2[4];
#pragma unroll
    for (int l = 0; l < 4; l++) {
        float g0 = ys[l], g1 = ys[l + 1], g2 = ys[l + 2];
        int kind = 1;
        if (l == 0 && eL) { g0 = ys[1]; g1 = ys[2]; g2 = ys[3]; kind = 0; }
        if (l == 3 && eR) { g0 = ys[2]; g1 = ys[3]; g2 = ys[4]; kind = 2; }
        float c1[3], c2[3];
        stencil_coeffs(g0, g1, g2, kind, c1, c2);
        C1Y0[l] = c1[0]; C1Y1[l] = c1[1]; C1Y2[l] = c1[2];
        C2Y0[l] = c2[0]; C2Y1[l] = c2[1]; C2Y2[l] = c2[2];
    }

    const float mu = mu_p[0];

#pragma unroll
    for (int m = 0; m < 4; m++) {
        const int i = i0 + m;

        // x coefficients for this row (warp-uniform)
        float cx1[3], cx2[3];
        {
            float g0 = xs[m], g1 = xs[m + 1], g2 = xs[m + 2];
            int kind = 1;
            if (m == 0 && firstB) { g0 = xs[1]; g1 = xs[2]; g2 = xs[3]; kind = 0; }
            if (m == 3 && lastB)  { g0 = xs[2]; g1 = xs[3]; g2 = xs[4]; kind = 2; }
            stencil_coeffs(g0, g1, g2, kind, cx1, cx2);
        }

        // select x-stencil data rows
        float4 u0, u1, u2, v0, v1, v2;
        if (m == 0) {
            u0 = firstB ? U[1] : U[0]; u1 = firstB ? U[2] : U[1]; u2 = firstB ? U[3] : U[2];
            v0 = firstB ? V[1] : V[0]; v1 = firstB ? V[2] : V[1]; v2 = firstB ? V[3] : V[2];
        } else if (m == 3) {
            u0 = lastB ? U[2] : U[3]; u1 = lastB ? U[3] : U[4]; u2 = lastB ? U[4] : U[5];
            v0 = lastB ? V[2] : V[3]; v1 = lastB ? V[3] : V[4]; v2 = lastB ? V[4] : V[5];
        } else {
            u0 = U[m]; u1 = U[m + 1]; u2 = U[m + 2];
            v0 = V[m]; v1 = V[m + 1]; v2 = V[m + 2];
        }

        // center row (global row i) is always U[m+1] / V[m+1]
        const float4 uc = U[m + 1];
        const float4 vc = V[m + 1];

        // y-neighbors via warp shuffle, patched at warp edges
        float uLm = __shfl_up_sync(FULLMASK, uc.w, 1);
        float vLm = __shfl_up_sync(FULLMASK, vc.w, 1);
        float uRm = __shfl_down_sync(FULLMASK, uc.x, 1);
        float vRm = __shfl_down_sync(FULLMASK, vc.x, 1);
        if (lane == 0)  { uLm = uLe[m]; vLm = vLe[m]; }
        if (lane == 31) { uRm = uRe[m]; vRm = vRe[m]; }

        const float u_vals[6] = {uLm, uc.x, uc.y, uc.z, uc.w, uRm};
        const float v_vals[6] = {vLm, vc.x, vc.y, vc.z, vc.w, vRm};
        const float AX0[4] = {u0.x, u0.y, u0.z, u0.w};
        const float AX1[4] = {u1.x, u1.y, u1.z, u1.w};
        const float AX2[4] = {u2.x, u2.y, u2.z, u2.w};
        const float BX0[4] = {v0.x, v0.y, v0.z, v0.w};
        const float BX1[4] = {v1.x, v1.y, v1.z, v1.w};
        const float BX2[4] = {v2.x, v2.y, v2.z, v2.w};

        float du[4], dv[4];
#pragma unroll
        for (int l = 0; l < 4; l++) {
            float f0 = u_vals[l], f1 = u_vals[l + 1], f2 = u_vals[l + 2];
            float g0 = v_vals[l], g1 = v_vals[l + 1], g2 = v_vals[l + 2];
            if (eL && l == 0) {         // one-sided at j=0: points 0,1,2
                f0 = u_vals[1]; f1 = u_vals[2]; f2 = u_vals[3];
                g0 = v_vals[1]; g1 = v_vals[2]; g2 = v_vals[3];
            }
            if (eR && l == 3) {         // one-sided at j=NY-1: points NY-3..NY-1
                f0 = u_vals[2]; f1 = u_vals[3]; f2 = u_vals[4];
                g0 = v_vals[2]; g1 = v_vals[3]; g2 = v_vals[4];
            }

            float d1yu = C1Y0[l] * f0 + C1Y1[l] * f1 + C1Y2[l] * f2;
            float d2yu = C2Y0[l] * f0 + C2Y1[l] * f1 + C2Y2[l] * f2;
            float d1yv = C1Y0[l] * g0 + C1Y1[l] * g1 + C1Y2[l] * g2;
            float d2yv = C2Y0[l] * g0 + C2Y1[l] * g1 + C2Y2[l] * g2;

            float d1xu = cx1[0] * AX0[l] + cx1[1] * AX1[l] + cx1[2] * AX2[l];
            float d2xu = cx2[0] * AX0[l] + cx2[1] * AX1[l] + cx2[2] * AX2[l];
            float d1xv = cx1[0] * BX0[l] + cx1[1] * BX1[l] + cx1[2] * BX2[l];
            float d2xv = cx2[0] * BX0[l] + cx2[1] * BX1[l] + cx2[2] * BX2[l];

            float ucen = u_vals[l + 1];
            float vcen = v_vals[l + 1];

            du[l] = mu * (d2yu + d2xu) - ucen * d1xu - vcen * d1yu + 0.01f;
            dv[l] = mu * (d2yv + d2xv) - ucen * d1xv - vcen * d1yv;

            int jj = j0 + l;
            if (jj == 0 || i == 0) { du[l] = 0.0f; dv[l] = 0.0f; }
            if (jj == NY - 1) du[l] = 0.0f;
        }

        *(float4*)(out + (size_t)i * NY + j0) =
            make_float4(du[0], du[1], du[2], du[3]);
        *(float4*)(out + (size_t)NX * NY + (size_t)i * NY + j0) =
            make_float4(dv[0], dv[1], dv[2], dv[3]);
    }
}

extern "C" void kernel_launch(void* const* d_in, const int* in_sizes, int n_in,
                              void* d_out, int out_size) {
    // inputs: 0=t(1), 1=state(2*NX*NY), 2=x(NX), 3=y(NY), 4=mu(1)
    const float* x_g   = (const float*)d_in[2];
    const float* y_g   = (const float*)d_in[3];
    const float* state = (const float*)d_in[1];
    const float* mu    = (const float*)d_in[4];
    float* out = (float*)d_out;

    dim3 blk(32, 4);                       // 128 threads
    dim3 grd((NY / 4) / 32, NX / (4 * 4)); // (32, 128)
    rhs_kernel<<<grd, blk>>>(state, x_g, y_g, mu, out);
}